// round 15
// baseline (speedup 1.0000x reference)
#include <cuda_runtime.h>
#include <cuda_fp16.h>
#include <cstdint>

#define HD 2048
#define NH 16
#define DH 128
#define BB 2
#define SQ 2048
#define MR (BB*SQ)   // 4096 rows

// ---------------------------------------------------------------------------
// Scratch (device globals; no allocations allowed)
// ---------------------------------------------------------------------------
__device__ __half g_Q16[(size_t)MR*HD];
__device__ __half g_K16[(size_t)MR*HD];
__device__ __half g_V16[(size_t)MR*HD];
__device__ __half g_A16[(size_t)MR*HD];
__device__ __half g_X16[(size_t)MR*HD];
__device__ __half g_Wt[4][(size_t)HD*HD];    // transposed [n][k], fp16; Q,K,V contiguous

// ---------------------------------------------------------------------------
// PTX helpers (compute_103-safe)
// ---------------------------------------------------------------------------
__device__ __forceinline__ uint32_t smem_to_u32(const void* p) {
    uint32_t a;
    asm("{ .reg .u64 t; cvta.to.shared.u64 t, %1; cvt.u32.u64 %0, t; }"
        : "=r"(a) : "l"(p));
    return a;
}
__device__ __forceinline__ void cp_async16(uint32_t s, const void* g) {
    asm volatile("cp.async.cg.shared.global [%0], [%1], 16;" :: "r"(s), "l"(g));
}
#define CP_COMMIT() asm volatile("cp.async.commit_group;" ::: "memory")
#define CP_WAIT(n)  asm volatile("cp.async.wait_group %0;" :: "n"(n) : "memory")

__device__ __forceinline__ void ldsm_x4(uint32_t& r0, uint32_t& r1,
                                        uint32_t& r2, uint32_t& r3, uint32_t addr) {
    asm volatile("ldmatrix.sync.aligned.m8n8.x4.shared.b16 {%0,%1,%2,%3}, [%4];"
        : "=r"(r0), "=r"(r1), "=r"(r2), "=r"(r3) : "r"(addr));
}
__device__ __forceinline__ void ldsm_x4_t(uint32_t& r0, uint32_t& r1,
                                          uint32_t& r2, uint32_t& r3, uint32_t addr) {
    asm volatile("ldmatrix.sync.aligned.m8n8.x4.trans.shared.b16 {%0,%1,%2,%3}, [%4];"
        : "=r"(r0), "=r"(r1), "=r"(r2), "=r"(r3) : "r"(addr));
}
__device__ __forceinline__ void mma_f16(float* c, const uint32_t* a,
                                        uint32_t b0, uint32_t b1) {
    asm volatile(
        "mma.sync.aligned.m16n8k16.row.col.f32.f16.f16.f32 "
        "{%0,%1,%2,%3}, {%4,%5,%6,%7}, {%8,%9}, {%0,%1,%2,%3};"
        : "+f"(c[0]), "+f"(c[1]), "+f"(c[2]), "+f"(c[3])
        : "r"(a[0]), "r"(a[1]), "r"(a[2]), "r"(a[3]), "r"(b0), "r"(b1));
}
__device__ __forceinline__ float ex2(float x) {
    float y;
    asm("ex2.approx.ftz.f32 %0, %1;" : "=f"(y) : "f"(x));
    return y;
}
__device__ __forceinline__ uint32_t pack_h2(float x, float y) {
    __half2 h(__float2half_rn(x), __float2half_rn(y));
    return *(uint32_t*)&h;
}

// ---------------------------------------------------------------------------
// Conversion kernels
// ---------------------------------------------------------------------------
__global__ __launch_bounds__(256) void cvt_h_kernel(
    const float4* __restrict__ in, __half* __restrict__ out, int n4)
{
    int i = blockIdx.x * 256 + threadIdx.x;
    if (i >= n4) return;
    float4 v = in[i];
    ((uint32_t*)out)[2*i+0] = pack_h2(v.x, v.y);
    ((uint32_t*)out)[2*i+1] = pack_h2(v.z, v.w);
}

// Batched: W[K,N] fp32 -> Wt[n][k] fp16. blockIdx.z selects weight.
__global__ __launch_bounds__(256) void cvt_wt_kernel(
    const float* __restrict__ W0, const float* __restrict__ W1,
    const float* __restrict__ W2, const float* __restrict__ W3,
    __half* __restrict__ outb)
{
    __shared__ float tile[32][33];
    const int z = blockIdx.z;
    const float* W = (z == 0) ? W0 : (z == 1) ? W1 : (z == 2) ? W2 : W3;
    __half* o = outb + (size_t)z * HD * HD;
    const int n0 = blockIdx.x * 32, k0 = blockIdx.y * 32;
    const int tx = threadIdx.x, ty = threadIdx.y;
    #pragma unroll
    for (int i = 0; i < 4; i++)
        tile[ty + 8*i][tx] = W[(size_t)(k0 + ty + 8*i) * HD + n0 + tx];
    __syncthreads();
    #pragma unroll
    for (int i = 0; i < 4; i++) {
        float v = tile[tx][ty + 8*i];
        o[(size_t)(n0 + ty + 8*i) * HD + k0 + tx] = __float2half_rn(v);
    }
}

// ---------------------------------------------------------------------------
// fp16 1-MMA GEMM: C = A16 @ W16^T + bias. CTA 128x128, KC=64, 8 warps.
// 3-stage cp.async pipeline (110.6KB, 2 CTAs/SM).
// MODE 0: fused QKV — Q/K/V out as fp16. MODE 1: O-proj — fp32 out + bias.
// ---------------------------------------------------------------------------
#define KC 64
#define NKT (HD / KC)                   // 32
#define GPITCH 144
#define GTILE (128 * GPITCH)            // 18432
#define GSTAGE (2 * GTILE)              // 36864: A, B
#define GEMM_SMEM (3 * GSTAGE)          // 110592

template<int MODE>
__global__ __launch_bounds__(256, 2) void gemm_mma_kernel(
    const __half* __restrict__ A16, const __half* __restrict__ Bh,
    const float* __restrict__ b0, const float* __restrict__ b1,
    const float* __restrict__ b2,
    __half* __restrict__ oQ, __half* __restrict__ oK, __half* __restrict__ oV,
    float* __restrict__ Cf)
{
    extern __shared__ __align__(128) char smem[];
    const uint32_t sbase = smem_to_u32(smem);
    const int tid  = threadIdx.x;
    const int wid  = tid >> 5;
    const int lane = tid & 31;
    const int bm = blockIdx.y * 128;
    const int bn = blockIdx.x * 128;
    const int wm = (wid >> 2) * 64;
    const int wn = (wid & 3) * 32;

    float acc[4][4][4];
    #pragma unroll
    for (int mt = 0; mt < 4; mt++)
        #pragma unroll
        for (int nt = 0; nt < 4; nt++)
            #pragma unroll
            for (int i = 0; i < 4; i++) acc[mt][nt][i] = 0.f;

    #define G_LOAD(SB, K0) do {                                                  \
        _Pragma("unroll")                                                        \
        for (int _i = 0; _i < 4; _i++) {                                         \
            int _lin = _i * 256 + tid;                                           \
            int _r = _lin >> 3, _c = _lin & 7;                                   \
            uint32_t _off = (uint32_t)_r * GPITCH + _c * 16;                     \
            size_t _ga = (size_t)(bm + _r) * HD + (K0) + _c * 8;                 \
            size_t _gb = (size_t)(bn + _r) * HD + (K0) + _c * 8;                 \
            cp_async16((SB) + 0*GTILE + _off, A16 + _ga);                        \
            cp_async16((SB) + 1*GTILE + _off, Bh  + _gb);                        \
        }                                                                        \
        CP_COMMIT();                                                             \
    } while (0)

    G_LOAD(sbase + 0 * GSTAGE, 0);
    G_LOAD(sbase + 1 * GSTAGE, KC);

    const int r8 = lane & 7;
    const int g  = lane >> 3;
    const uint32_t a_row_add = (uint32_t)(r8 + ((g & 1) ? 8 : 0)) * GPITCH + ((g & 2) ? 16 : 0);
    const uint32_t b_row_add = (uint32_t)(r8 + ((g >= 2) ? 8 : 0)) * GPITCH + ((g & 1) ? 16 : 0);

    for (int t = 0; t < NKT; t++) {
        if (t < NKT - 1) { CP_WAIT(1); } else { CP_WAIT(0); }
        __syncthreads();
        if (t + 2 < NKT)
            G_LOAD(sbase + ((t + 2) % 3) * GSTAGE, (t + 2) * KC);

        const uint32_t sb = sbase + (t % 3) * GSTAGE;
        #pragma unroll
        for (int ks = 0; ks < 4; ks++) {
            uint32_t bh[2][4];
            #pragma unroll
            for (int p = 0; p < 2; p++) {
                uint32_t addr = sb + 1*GTILE + (uint32_t)(wn + p * 16) * GPITCH + ks * 32 + b_row_add;
                ldsm_x4(bh[p][0], bh[p][1], bh[p][2], bh[p][3], addr);
            }
            #pragma unroll
            for (int mt = 0; mt < 4; mt++) {
                uint32_t ah[4];
                uint32_t addr = sb + (uint32_t)(wm + mt * 16) * GPITCH + ks * 32 + a_row_add;
                ldsm_x4(ah[0], ah[1], ah[2], ah[3], addr);
                #pragma unroll
                for (int nt = 0; nt < 4; nt++) {
                    uint32_t bb0 = bh[nt >> 1][(nt & 1) * 2 + 0];
                    uint32_t bb1 = bh[nt >> 1][(nt & 1) * 2 + 1];
                    mma_f16(acc[mt][nt], ah, bb0, bb1);
                }
            }
        }
        __syncthreads();
    }

    const int er = lane >> 2;
    const int ec = (lane & 3) * 2;

    if (MODE == 0) {
        const int w  = bn >> 11;            // 0=Q,1=K,2=V
        const int ln = (bn & 2047) + wn;
        const float* bias = (w == 0) ? b0 : (w == 1) ? b1 : b2;
        __half* dst = (w == 0) ? oQ : (w == 1) ? oK : oV;
        #pragma unroll
        for (int mt = 0; mt < 4; mt++) {
            #pragma unroll
            for (int nt = 0; nt < 4; nt++) {
                int row = bm + wm + mt * 16 + er;
                int col = ln + nt * 8 + ec;
                float bb0 = bias[col], bb1 = bias[col + 1];
                *(uint32_t*)&dst[(size_t)row * HD + col] =
                    pack_h2(acc[mt][nt][0] + bb0, acc[mt][nt][1] + bb1);
                *(uint32_t*)&dst[(size_t)(row + 8) * HD + col] =
                    pack_h2(acc[mt][nt][2] + bb0, acc[mt][nt][3] + bb1);
            }
        }
    } else {
        #pragma unroll
        for (int mt = 0; mt < 4; mt++) {
            #pragma unroll
            for (int nt = 0; nt < 4; nt++) {
                int row = bm + wm + mt * 16 + er;
                int col = bn + wn + nt * 8 + ec;
                float bb0 = b0[col], bb1 = b0[col + 1];
                *(float2*)&Cf[(size_t)row * HD + col] =
                    make_float2(acc[mt][nt][0] + bb0, acc[mt][nt][1] + bb1);
                *(float2*)&Cf[(size_t)(row + 8) * HD + col] =
                    make_float2(acc[mt][nt][2] + bb0, acc[mt][nt][3] + bb1);
            }
        }
    }
}

// ---------------------------------------------------------------------------
// Tensor-core flash attention v2: 8 warps / 128 q-rows per CTA (1 CTA/SM),
// 128-key double-buffered stages, two 64-key softmax sub-iterations per stage.
// Halves cp.async/L2 traffic and barrier count vs round 14.
// ---------------------------------------------------------------------------
#define AVP 272
#define KTB128 (128 * AVP)          // 34816 per tile (128 rows x 128 fp16)
#define STB128 (2 * KTB128)         // 69632 per stage (K16, V16)
#define ATTN_SMEM (2 * STB128)      // 139264
#define QSTG 0                      // Q staging (34.8KB) overlays stage 0

__global__ __launch_bounds__(256, 1) void attn_mma_kernel(
    const __half* __restrict__ Q16,
    const __half* __restrict__ K16, const __half* __restrict__ V16,
    const int* __restrict__ mask,
    __half* __restrict__ A16)
{
    extern __shared__ __align__(128) char smem[];
    const uint32_t sbase = smem_to_u32(smem);
    const int tid  = threadIdx.x;
    const int wid  = tid >> 5;          // 0..7
    const int lane = tid & 31;
    const int q0 = blockIdx.x * 128;
    const int h  = blockIdx.y;
    const int b  = blockIdx.z;
    const int hc = h * DH;

    const int r8 = lane & 7;
    const int g  = lane >> 3;
    const uint32_t a_add = (uint32_t)(r8 + ((g & 1) ? 8 : 0)) * AVP + ((g & 2) ? 16 : 0);
    const uint32_t b_add = (uint32_t)(r8 + ((g >= 2) ? 8 : 0)) * AVP + ((g & 1) ? 16 : 0);
    const uint32_t v_add = (uint32_t)(r8 + ((g & 1) ? 8 : 0)) * AVP + ((g >> 1) ? 16 : 0);

    // ---- stage Q (128 x 128 fp16) and pull into registers ----
    {
        #pragma unroll
        for (int i = 0; i < 8; i++) {
            int lin = i * 256 + tid;       // 2048 16B-chunks
            int r = lin >> 4, c = lin & 15;
            size_t gq = (size_t)(b * SQ + q0 + r) * HD + hc + c * 8;
            cp_async16(sbase + QSTG + (uint32_t)r * AVP + c * 16, Q16 + gq);
        }
        CP_COMMIT();
        CP_WAIT(0);
        __syncthreads();
    }

    uint32_t qh[8][4];
    #pragma unroll
    for (int ks = 0; ks < 8; ks++) {
        uint32_t addr = (uint32_t)(16 * wid) * AVP + ks * 32 + a_add;
        ldsm_x4(qh[ks][0], qh[ks][1], qh[ks][2], qh[ks][3], sbase + QSTG + addr);
    }
    __syncthreads();   // Q staging space becomes K/V stages

    #define LOAD_STAGE128(T, STAGE) do {                                         \
        const uint32_t _sb = sbase + (STAGE) * STB128;                           \
        _Pragma("unroll")                                                        \
        for (int _i = 0; _i < 8; _i++) {                                         \
            int _lin = _i * 256 + tid;        /* 2048 16B-chunks per tensor */   \
            int _r = _lin >> 4, _c = _lin & 15;                                  \
            size_t _gk = (size_t)(b * SQ + (T) * 128 + _r) * HD + hc + _c * 8;   \
            uint32_t _off = (uint32_t)_r * AVP + _c * 16;                        \
            cp_async16(_sb + 0*KTB128 + _off, K16 + _gk);                        \
            cp_async16(_sb + 1*KTB128 + _off, V16 + _gk);                        \
        }                                                                        \
        CP_COMMIT();                                                             \
    } while (0)

    LOAD_STAGE128(0, 0);

    float m0 = -1e30f, m1 = -1e30f, l0 = 0.f, l1 = 0.f;
    float o[16][4];
    #pragma unroll
    for (int nt = 0; nt < 16; nt++)
        #pragma unroll
        for (int i = 0; i < 4; i++) o[nt][i] = 0.f;

    const float scale2 = 0.08838834764831845f * 1.4426950408889634f;
    const int row0 = q0 + 16 * wid + (lane >> 2);
    const int c2 = (lane & 3) * 2;
    const int* mrow0 = mask + ((size_t)b * SQ + row0) * SQ;
    const int* mrow1 = mrow0 + 8 * SQ;

    for (int t = 0; t < SQ / 128; t++) {
        if (t + 1 < SQ / 128) { LOAD_STAGE128(t + 1, (t + 1) & 1); CP_WAIT(1); }
        else CP_WAIT(0);
        __syncthreads();

        const uint32_t sb = sbase + (t & 1) * STB128;

        #pragma unroll
        for (int sub = 0; sub < 2; sub++) {
            const uint32_t krow = (uint32_t)(sub * 64);

            // ---- S = Q16 K16^T over 64 keys ----
            float s[8][4];
            #pragma unroll
            for (int j = 0; j < 8; j++)
                #pragma unroll
                for (int i = 0; i < 4; i++) s[j][i] = 0.f;

            #pragma unroll
            for (int ks = 0; ks < 8; ks++) {
                #pragma unroll
                for (int p = 0; p < 4; p++) {
                    uint32_t kh[4];
                    uint32_t addr = sb + (krow + 16 * p) * AVP + ks * 32 + b_add;
                    ldsm_x4(kh[0], kh[1], kh[2], kh[3], addr);
                    mma_f16(s[2*p],   qh[ks], kh[0], kh[1]);
                    mma_f16(s[2*p+1], qh[ks], kh[2], kh[3]);
                }
            }

            // ---- mask + scale + online softmax (base-2, warp-private) ----
            const int k0 = t * 128 + sub * 64;
            float mx0 = -1e30f, mx1 = -1e30f;
            #pragma unroll
            for (int j = 0; j < 8; j++) {
                int2 mm0 = *(const int2*)&mrow0[k0 + 8*j + c2];
                int2 mm1 = *(const int2*)&mrow1[k0 + 8*j + c2];
                s[j][0] = mm0.x ? s[j][0] * scale2 : -1e30f;
                s[j][1] = mm0.y ? s[j][1] * scale2 : -1e30f;
                s[j][2] = mm1.x ? s[j][2] * scale2 : -1e30f;
                s[j][3] = mm1.y ? s[j][3] * scale2 : -1e30f;
                mx0 = fmaxf(mx0, fmaxf(s[j][0], s[j][1]));
                mx1 = fmaxf(mx1, fmaxf(s[j][2], s[j][3]));
            }
            mx0 = fmaxf(mx0, __shfl_xor_sync(0xffffffffu, mx0, 1));
            mx0 = fmaxf(mx0, __shfl_xor_sync(0xffffffffu, mx0, 2));
            mx1 = fmaxf(mx1, __shfl_xor_sync(0xffffffffu, mx1, 1));
            mx1 = fmaxf(mx1, __shfl_xor_sync(0xffffffffu, mx1, 2));

            float mn0 = fmaxf(m0, mx0), mn1 = fmaxf(m1, mx1);
            float corr0 = ex2(m0 - mn0), corr1 = ex2(m1 - mn1);
            bool upd = (mn0 != m0) || (mn1 != m1);
            m0 = mn0; m1 = mn1;

            float ps0 = 0.f, ps1 = 0.f;
            #pragma unroll
            for (int j = 0; j < 8; j++) {
                s[j][0] = ex2(s[j][0] - m0);
                s[j][1] = ex2(s[j][1] - m0);
                s[j][2] = ex2(s[j][2] - m1);
                s[j][3] = ex2(s[j][3] - m1);
                ps0 += s[j][0] + s[j][1];
                ps1 += s[j][2] + s[j][3];
            }
            ps0 += __shfl_xor_sync(0xffffffffu, ps0, 1);
            ps0 += __shfl_xor_sync(0xffffffffu, ps0, 2);
            ps1 += __shfl_xor_sync(0xffffffffu, ps1, 1);
            ps1 += __shfl_xor_sync(0xffffffffu, ps1, 2);
            l0 = l0 * corr0 + ps0;
            l1 = l1 * corr1 + ps1;

            if (__any_sync(0xffffffffu, upd)) {
                #pragma unroll
                for (int nt = 0; nt < 16; nt++) {
                    o[nt][0] *= corr0; o[nt][1] *= corr0;
                    o[nt][2] *= corr1; o[nt][3] *= corr1;
                }
            }

            // ---- O += P16 V16 over 64 keys ----
            #pragma unroll
            for (int ks2 = 0; ks2 < 4; ks2++) {
                uint32_t ph[4];
                ph[0] = pack_h2(s[2*ks2][0],   s[2*ks2][1]);
                ph[1] = pack_h2(s[2*ks2][2],   s[2*ks2][3]);
                ph[2] = pack_h2(s[2*ks2+1][0], s[2*ks2+1][1]);
                ph[3] = pack_h2(s[2*ks2+1][2], s[2*ks2+1][3]);
                #pragma unroll
                for (int dp = 0; dp < 8; dp++) {
                    uint32_t vh[4];
                    uint32_t addr = sb + 1*KTB128 + (krow + 16 * ks2) * AVP + dp * 32 + v_add;
                    ldsm_x4_t(vh[0], vh[1], vh[2], vh[3], addr);
                    mma_f16(o[2*dp],   ph, vh[0], vh[1]);
                    mma_f16(o[2*dp+1], ph, vh[2], vh[3]);
                }
            }
        }
        __syncthreads();
    }

    // ---- epilogue: normalize, single fp16 out ----
    const float inv0 = 1.f / l0, inv1 = 1.f / l1;
    const size_t ob0 = (size_t)(b * SQ + row0) * HD + hc;
    const size_t ob1 = ob0 + (size_t)8 * HD;
    #pragma unroll
    for (int nt = 0; nt < 16; nt++) {
        int col = 8 * nt + c2;
        *(uint32_t*)&A16[ob0 + col] = pack_h2(o[nt][0] * inv0, o[nt][1] * inv0);
        *(uint32_t*)&A16[ob1 + col] = pack_h2(o[nt][2] * inv1, o[nt][3] * inv1);
    }
}

// ---------------------------------------------------------------------------

extern "C" void kernel_launch(void* const* d_in, const int* in_sizes, int n_in,
                              void* d_out, int out_size)
{
    const float* X   = (const float*)d_in[0];
    const int*   msk = (const int*)  d_in[1];
    const float* Wq  = (const float*)d_in[2];
    const float* bq  = (const float*)d_in[3];
    const float* Wk  = (const float*)d_in[4];
    const float* bk  = (const float*)d_in[5];
    const float* Wv  = (const float*)d_in[6];
    const float* bv  = (const float*)d_in[7];
    const float* Wo  = (const float*)d_in[8];
    const float* bo  = (const float*)d_in[9];
    float* out = (float*)d_out;

    __half *Q16, *K16, *V16, *A16, *X16, *Wt;
    cudaGetSymbolAddress((void**)&Q16, g_Q16);
    cudaGetSymbolAddress((void**)&K16, g_K16);
    cudaGetSymbolAddress((void**)&V16, g_V16);
    cudaGetSymbolAddress((void**)&A16, g_A16);
    cudaGetSymbolAddress((void**)&X16, g_X16);
    cudaGetSymbolAddress((void**)&Wt,  g_Wt);

    const size_t WSZ = (size_t)HD * HD;
    const int n4 = MR * HD / 4;

    cudaFuncSetAttribute(gemm_mma_kernel<0>,
                         cudaFuncAttributeMaxDynamicSharedMemorySize, GEMM_SMEM);
    cudaFuncSetAttribute(gemm_mma_kernel<1>,
                         cudaFuncAttributeMaxDynamicSharedMemorySize, GEMM_SMEM);
    cudaFuncSetAttribute(attn_mma_kernel,
                         cudaFuncAttributeMaxDynamicSharedMemorySize, ATTN_SMEM);

    // 1. X -> fp16; batched weight transpose -> fp16
    cvt_h_kernel<<<n4 / 256, 256>>>((const float4*)X, X16, n4);
    dim3 wg(HD / 32, HD / 32, 4), wb(32, 8);
    cvt_wt_kernel<<<wg, wb>>>(Wq, Wk, Wv, Wo, Wt);

    // 2. Fused Q/K/V projection (1-MMA, 3-stage) -> fp16 outputs
    dim3 gq(3 * HD / 128, MR / 128);   // (48, 32)
    gemm_mma_kernel<0><<<gq, 256, GEMM_SMEM>>>(
        X16, Wt, bq, bk, bv, Q16, K16, V16, nullptr);

    // 3. fp16 1-MMA flash attention v2 (128 q-rows/CTA, 128-key stages)
    dim3 ga(SQ / 128, NH, BB);         // (16, 16, 2) = 512 CTAs
    attn_mma_kernel<<<ga, 256, ATTN_SMEM>>>(Q16, K16, V16, msk, A16);

    // 4. output projection (1-MMA, 3-stage) -> fp32 out
    dim3 go(HD / 128, MR / 128);       // (16, 32)
    gemm_mma_kernel<1><<<go, 256, GEMM_SMEM>>>(
        A16, Wt + 3*WSZ, bo, bo, bo,
        nullptr, nullptr, nullptr, out);
}

// round 16
// speedup vs baseline: 1.1051x; 1.1051x over previous
#include <cuda_runtime.h>
#include <cuda_fp16.h>
#include <cstdint>

#define HD 2048
#define NH 16
#define DH 128
#define BB 2
#define SQ 2048
#define MR (BB*SQ)   // 4096 rows

// ---------------------------------------------------------------------------
// Scratch (device globals; no allocations allowed)
// ---------------------------------------------------------------------------
__device__ __half g_Q16[(size_t)MR*HD];
__device__ __half g_K16[(size_t)MR*HD];
__device__ __half g_V16[(size_t)MR*HD];
__device__ __half g_A16[(size_t)MR*HD];
__device__ __half g_X16[(size_t)MR*HD];
__device__ __half g_Wt[4][(size_t)HD*HD];    // transposed [n][k], fp16; Q,K,V contiguous
__device__ uint32_t g_Mbits[(size_t)MR * (SQ/32)];   // 1 bit per mask entry

// ---------------------------------------------------------------------------
// PTX helpers (compute_103-safe)
// ---------------------------------------------------------------------------
__device__ __forceinline__ uint32_t smem_to_u32(const void* p) {
    uint32_t a;
    asm("{ .reg .u64 t; cvta.to.shared.u64 t, %1; cvt.u32.u64 %0, t; }"
        : "=r"(a) : "l"(p));
    return a;
}
__device__ __forceinline__ void cp_async16(uint32_t s, const void* g) {
    asm volatile("cp.async.cg.shared.global [%0], [%1], 16;" :: "r"(s), "l"(g));
}
#define CP_COMMIT() asm volatile("cp.async.commit_group;" ::: "memory")
#define CP_WAIT(n)  asm volatile("cp.async.wait_group %0;" :: "n"(n) : "memory")

__device__ __forceinline__ void ldsm_x4(uint32_t& r0, uint32_t& r1,
                                        uint32_t& r2, uint32_t& r3, uint32_t addr) {
    asm volatile("ldmatrix.sync.aligned.m8n8.x4.shared.b16 {%0,%1,%2,%3}, [%4];"
        : "=r"(r0), "=r"(r1), "=r"(r2), "=r"(r3) : "r"(addr));
}
__device__ __forceinline__ void ldsm_x4_t(uint32_t& r0, uint32_t& r1,
                                          uint32_t& r2, uint32_t& r3, uint32_t addr) {
    asm volatile("ldmatrix.sync.aligned.m8n8.x4.trans.shared.b16 {%0,%1,%2,%3}, [%4];"
        : "=r"(r0), "=r"(r1), "=r"(r2), "=r"(r3) : "r"(addr));
}
__device__ __forceinline__ void mma_f16(float* c, const uint32_t* a,
                                        uint32_t b0, uint32_t b1) {
    asm volatile(
        "mma.sync.aligned.m16n8k16.row.col.f32.f16.f16.f32 "
        "{%0,%1,%2,%3}, {%4,%5,%6,%7}, {%8,%9}, {%0,%1,%2,%3};"
        : "+f"(c[0]), "+f"(c[1]), "+f"(c[2]), "+f"(c[3])
        : "r"(a[0]), "r"(a[1]), "r"(a[2]), "r"(a[3]), "r"(b0), "r"(b1));
}
__device__ __forceinline__ float ex2(float x) {
    float y;
    asm("ex2.approx.ftz.f32 %0, %1;" : "=f"(y) : "f"(x));
    return y;
}
__device__ __forceinline__ uint32_t pack_h2(float x, float y) {
    __half2 h(__float2half_rn(x), __float2half_rn(y));
    return *(uint32_t*)&h;
}

// ---------------------------------------------------------------------------
// Conversion kernels
// ---------------------------------------------------------------------------
__global__ __launch_bounds__(256) void cvt_h_kernel(
    const float4* __restrict__ in, __half* __restrict__ out, int n4)
{
    int i = blockIdx.x * 256 + threadIdx.x;
    if (i >= n4) return;
    float4 v = in[i];
    ((uint32_t*)out)[2*i+0] = pack_h2(v.x, v.y);
    ((uint32_t*)out)[2*i+1] = pack_h2(v.z, v.w);
}

__global__ __launch_bounds__(256) void cvt_wt_kernel(
    const float* __restrict__ W0, const float* __restrict__ W1,
    const float* __restrict__ W2, const float* __restrict__ W3,
    __half* __restrict__ outb)
{
    __shared__ float tile[32][33];
    const int z = blockIdx.z;
    const float* W = (z == 0) ? W0 : (z == 1) ? W1 : (z == 2) ? W2 : W3;
    __half* o = outb + (size_t)z * HD * HD;
    const int n0 = blockIdx.x * 32, k0 = blockIdx.y * 32;
    const int tx = threadIdx.x, ty = threadIdx.y;
    #pragma unroll
    for (int i = 0; i < 4; i++)
        tile[ty + 8*i][tx] = W[(size_t)(k0 + ty + 8*i) * HD + n0 + tx];
    __syncthreads();
    #pragma unroll
    for (int i = 0; i < 4; i++) {
        float v = tile[tx][ty + 8*i];
        o[(size_t)(n0 + ty + 8*i) * HD + k0 + tx] = __float2half_rn(v);
    }
}

// Pack int32 mask -> 1 bit per entry. Each thread: 32 consecutive ints (1 line).
__global__ __launch_bounds__(256) void cvt_mask_kernel(
    const int* __restrict__ mask, uint32_t* __restrict__ mbits, int nwords)
{
    int w = blockIdx.x * 256 + threadIdx.x;
    if (w >= nwords) return;
    const int* p = mask + (size_t)w * 32;
    uint32_t b = 0;
    #pragma unroll
    for (int i = 0; i < 32; i++)
        b |= (p[i] != 0 ? 1u : 0u) << i;
    mbits[w] = b;
}

// ---------------------------------------------------------------------------
// fp16 1-MMA GEMM v2: CTA 128x128, 4 warps (128 thr), warp tile 64x64.
// Fewer ldsm/cp.async per MMA (issue-bound fix). KC=64, 2-stage, 2 CTAs/SM.
// MODE 0: fused QKV — Q/K/V out as fp16. MODE 1: O-proj — fp32 out + bias.
// ---------------------------------------------------------------------------
#define KC 64
#define NKT (HD / KC)                   // 32
#define GPITCH 144
#define GTILE (128 * GPITCH)            // 18432
#define GSTAGE (2 * GTILE)              // 36864: A, B
#define GEMM_SMEM (2 * GSTAGE)          // 73728

template<int MODE>
__global__ __launch_bounds__(128, 2) void gemm_mma_kernel(
    const __half* __restrict__ A16, const __half* __restrict__ Bh,
    const float* __restrict__ b0, const float* __restrict__ b1,
    const float* __restrict__ b2,
    __half* __restrict__ oQ, __half* __restrict__ oK, __half* __restrict__ oV,
    float* __restrict__ Cf)
{
    extern __shared__ __align__(128) char smem[];
    const uint32_t sbase = smem_to_u32(smem);
    const int tid  = threadIdx.x;
    const int wid  = tid >> 5;          // 0..3
    const int lane = tid & 31;
    const int bm = blockIdx.y * 128;
    const int bn = blockIdx.x * 128;
    const int wm = (wid >> 1) * 64;     // warp row offset
    const int wn = (wid & 1) * 64;      // warp col offset

    float acc[4][8][4];                 // mt x nt(8 of n8) x 4
    #pragma unroll
    for (int mt = 0; mt < 4; mt++)
        #pragma unroll
        for (int nt = 0; nt < 8; nt++)
            #pragma unroll
            for (int i = 0; i < 4; i++) acc[mt][nt][i] = 0.f;

    // stage loader: 2 tiles x 1024 16B-chunks, 128 threads -> 16 per thread
    #define G_LOAD(SB, K0) do {                                                  \
        _Pragma("unroll")                                                        \
        for (int _i = 0; _i < 8; _i++) {                                         \
            int _lin = _i * 128 + tid;                                           \
            int _r = _lin >> 3, _c = _lin & 7;                                   \
            uint32_t _off = (uint32_t)_r * GPITCH + _c * 16;                     \
            size_t _ga = (size_t)(bm + _r) * HD + (K0) + _c * 8;                 \
            size_t _gb = (size_t)(bn + _r) * HD + (K0) + _c * 8;                 \
            cp_async16((SB) + 0*GTILE + _off, A16 + _ga);                        \
            cp_async16((SB) + 1*GTILE + _off, Bh  + _gb);                        \
        }                                                                        \
        CP_COMMIT();                                                             \
    } while (0)

    G_LOAD(sbase, 0);

    const int r8 = lane & 7;
    const int g  = lane >> 3;
    const uint32_t a_row_add = (uint32_t)(r8 + ((g & 1) ? 8 : 0)) * GPITCH + ((g & 2) ? 16 : 0);
    const uint32_t b_row_add = (uint32_t)(r8 + ((g >= 2) ? 8 : 0)) * GPITCH + ((g & 1) ? 16 : 0);

    for (int t = 0; t < NKT; t++) {
        if (t + 1 < NKT) {
            G_LOAD(sbase + ((t + 1) & 1) * GSTAGE, (t + 1) * KC);
            CP_WAIT(1);
        } else {
            CP_WAIT(0);
        }
        __syncthreads();

        const uint32_t sb = sbase + (t & 1) * GSTAGE;
        #pragma unroll
        for (int ks = 0; ks < 4; ks++) {
            uint32_t bh[4][4];
            #pragma unroll
            for (int p = 0; p < 4; p++) {
                uint32_t addr = sb + 1*GTILE + (uint32_t)(wn + p * 16) * GPITCH + ks * 32 + b_row_add;
                ldsm_x4(bh[p][0], bh[p][1], bh[p][2], bh[p][3], addr);
            }
            #pragma unroll
            for (int mt = 0; mt < 4; mt++) {
                uint32_t ah[4];
                uint32_t addr = sb + (uint32_t)(wm + mt * 16) * GPITCH + ks * 32 + a_row_add;
                ldsm_x4(ah[0], ah[1], ah[2], ah[3], addr);
                #pragma unroll
                for (int nt = 0; nt < 8; nt++) {
                    uint32_t bb0 = bh[nt >> 1][(nt & 1) * 2 + 0];
                    uint32_t bb1 = bh[nt >> 1][(nt & 1) * 2 + 1];
                    mma_f16(acc[mt][nt], ah, bb0, bb1);
                }
            }
        }
        __syncthreads();
    }

    const int er = lane >> 2;
    const int ec = (lane & 3) * 2;

    if (MODE == 0) {
        const int w  = bn >> 11;            // 0=Q,1=K,2=V
        const int ln = (bn & 2047) + wn;
        const float* bias = (w == 0) ? b0 : (w == 1) ? b1 : b2;
        __half* dst = (w == 0) ? oQ : (w == 1) ? oK : oV;
        #pragma unroll
        for (int mt = 0; mt < 4; mt++) {
            #pragma unroll
            for (int nt = 0; nt < 8; nt++) {
                int row = bm + wm + mt * 16 + er;
                int col = ln + nt * 8 + ec;
                float bb0 = bias[col], bb1 = bias[col + 1];
                *(uint32_t*)&dst[(size_t)row * HD + col] =
                    pack_h2(acc[mt][nt][0] + bb0, acc[mt][nt][1] + bb1);
                *(uint32_t*)&dst[(size_t)(row + 8) * HD + col] =
                    pack_h2(acc[mt][nt][2] + bb0, acc[mt][nt][3] + bb1);
            }
        }
    } else {
        #pragma unroll
        for (int mt = 0; mt < 4; mt++) {
            #pragma unroll
            for (int nt = 0; nt < 8; nt++) {
                int row = bm + wm + mt * 16 + er;
                int col = bn + wn + nt * 8 + ec;
                float bb0 = b0[col], bb1 = b0[col + 1];
                *(float2*)&Cf[(size_t)row * HD + col] =
                    make_float2(acc[mt][nt][0] + bb0, acc[mt][nt][1] + bb1);
                *(float2*)&Cf[(size_t)(row + 8) * HD + col] =
                    make_float2(acc[mt][nt][2] + bb0, acc[mt][nt][3] + bb1);
            }
        }
    }
}

// ---------------------------------------------------------------------------
// Tensor-core flash attention (round-14 structure: 4 warps / 64 q-rows,
// 64-key chunks, 2 CTAs/SM) + bitmask mask path.
// ---------------------------------------------------------------------------
#define AVP 272
#define KTB64 (64 * AVP)            // 17408 per tile (64 rows x 128 fp16)
#define STB64 (2 * KTB64)           // 34816 per stage (K16, V16)
#define ATTN_SMEM (2 * STB64)       // 69632
#define QSTG 0                      // Q staging overlays the K/V stages

__global__ __launch_bounds__(128, 2) void attn_mma_kernel(
    const __half* __restrict__ Q16,
    const __half* __restrict__ K16, const __half* __restrict__ V16,
    const uint32_t* __restrict__ mbits,
    __half* __restrict__ A16)
{
    extern __shared__ __align__(128) char smem[];
    const uint32_t sbase = smem_to_u32(smem);
    const int tid  = threadIdx.x;
    const int wid  = tid >> 5;
    const int lane = tid & 31;
    const int q0 = blockIdx.x * 64;
    const int h  = blockIdx.y;
    const int b  = blockIdx.z;
    const int hc = h * DH;

    const int r8 = lane & 7;
    const int g  = lane >> 3;
    const uint32_t a_add = (uint32_t)(r8 + ((g & 1) ? 8 : 0)) * AVP + ((g & 2) ? 16 : 0);
    const uint32_t b_add = (uint32_t)(r8 + ((g >= 2) ? 8 : 0)) * AVP + ((g & 1) ? 16 : 0);
    const uint32_t v_add = (uint32_t)(r8 + ((g & 1) ? 8 : 0)) * AVP + ((g >> 1) ? 16 : 0);

    // ---- stage Q (64 x 128 fp16) and pull into registers ----
    {
        #pragma unroll
        for (int i = 0; i < 8; i++) {
            int lin = i * 128 + tid;       // 1024 16B-chunks
            int r = lin >> 4, c = lin & 15;
            size_t gq = (size_t)(b * SQ + q0 + r) * HD + hc + c * 8;
            cp_async16(sbase + QSTG + (uint32_t)r * AVP + c * 16, Q16 + gq);
        }
        CP_COMMIT();
        CP_WAIT(0);
        __syncthreads();
    }

    uint32_t qh[8][4];
    #pragma unroll
    for (int ks = 0; ks < 8; ks++) {
        uint32_t addr = (uint32_t)(16 * wid) * AVP + ks * 32 + a_add;
        ldsm_x4(qh[ks][0], qh[ks][1], qh[ks][2], qh[ks][3], sbase + QSTG + addr);
    }
    __syncthreads();   // Q staging space becomes K/V stages

    #define LOAD_CHUNK64(T, STAGE) do {                                          \
        const uint32_t _sb = sbase + (STAGE) * STB64;                            \
        _Pragma("unroll")                                                        \
        for (int _i = 0; _i < 8; _i++) {                                         \
            int _lin = _i * 128 + tid;        /* 1024 16B-chunks per tensor */   \
            int _r = _lin >> 4, _c = _lin & 15;                                  \
            size_t _gk = (size_t)(b * SQ + (T) * 64 + _r) * HD + hc + _c * 8;    \
            uint32_t _off = (uint32_t)_r * AVP + _c * 16;                        \
            cp_async16(_sb + 0*KTB64 + _off, K16 + _gk);                         \
            cp_async16(_sb + 1*KTB64 + _off, V16 + _gk);                         \
        }                                                                        \
        CP_COMMIT();                                                             \
    } while (0)

    LOAD_CHUNK64(0, 0);

    float m0 = -1e30f, m1 = -1e30f, l0 = 0.f, l1 = 0.f;
    float o[16][4];
    #pragma unroll
    for (int nt = 0; nt < 16; nt++)
        #pragma unroll
        for (int i = 0; i < 4; i++) o[nt][i] = 0.f;

    const float scale2 = 0.08838834764831845f * 1.4426950408889634f;
    const int row0 = q0 + 16 * wid + (lane >> 2);
    const int c2 = (lane & 3) * 2;
    const uint32_t* mb0 = mbits + ((size_t)(b * SQ) + row0) * (SQ / 32);
    const uint32_t* mb1 = mb0 + (size_t)8 * (SQ / 32);

    for (int t = 0; t < SQ / 64; t++) {
        if (t + 1 < SQ / 64) { LOAD_CHUNK64(t + 1, (t + 1) & 1); CP_WAIT(1); }
        else CP_WAIT(0);
        __syncthreads();

        const uint32_t sb = sbase + (t & 1) * STB64;

        // ---- S = Q16 K16^T over 64 keys ----
        float s[8][4];
        #pragma unroll
        for (int j = 0; j < 8; j++)
            #pragma unroll
            for (int i = 0; i < 4; i++) s[j][i] = 0.f;

        #pragma unroll
        for (int ks = 0; ks < 8; ks++) {
            #pragma unroll
            for (int p = 0; p < 4; p++) {
                uint32_t kh[4];
                uint32_t addr = sb + (uint32_t)(16 * p) * AVP + ks * 32 + b_add;
                ldsm_x4(kh[0], kh[1], kh[2], kh[3], addr);
                mma_f16(s[2*p],   qh[ks], kh[0], kh[1]);
                mma_f16(s[2*p+1], qh[ks], kh[2], kh[3]);
            }
        }

        // ---- bitmask + scale + online softmax (base-2, warp-private) ----
        uint2 w0 = *(const uint2*)&mb0[t * 2];
        uint2 w1 = *(const uint2*)&mb1[t * 2];
        uint64_t mm0 = (uint64_t)w0.x | ((uint64_t)w0.y << 32);
        uint64_t mm1 = (uint64_t)w1.x | ((uint64_t)w1.y << 32);

        float mx0 = -1e30f, mx1 = -1e30f;
        #pragma unroll
        for (int j = 0; j < 8; j++) {
            uint32_t f0 = (uint32_t)(mm0 >> (8 * j + c2));
            uint32_t f1 = (uint32_t)(mm1 >> (8 * j + c2));
            s[j][0] = (f0 & 1u) ? s[j][0] * scale2 : -1e30f;
            s[j][1] = (f0 & 2u) ? s[j][1] * scale2 : -1e30f;
            s[j][2] = (f1 & 1u) ? s[j][2] * scale2 : -1e30f;
            s[j][3] = (f1 & 2u) ? s[j][3] * scale2 : -1e30f;
            mx0 = fmaxf(mx0, fmaxf(s[j][0], s[j][1]));
            mx1 = fmaxf(mx1, fmaxf(s[j][2], s[j][3]));
        }
        mx0 = fmaxf(mx0, __shfl_xor_sync(0xffffffffu, mx0, 1));
        mx0 = fmaxf(mx0, __shfl_xor_sync(0xffffffffu, mx0, 2));
        mx1 = fmaxf(mx1, __shfl_xor_sync(0xffffffffu, mx1, 1));
        mx1 = fmaxf(mx1, __shfl_xor_sync(0xffffffffu, mx1, 2));

        float mn0 = fmaxf(m0, mx0), mn1 = fmaxf(m1, mx1);
        float corr0 = ex2(m0 - mn0), corr1 = ex2(m1 - mn1);
        bool upd = (mn0 != m0) || (mn1 != m1);
        m0 = mn0; m1 = mn1;

        float ps0 = 0.f, ps1 = 0.f;
        #pragma unroll
        for (int j = 0; j < 8; j++) {
            s[j][0] = ex2(s[j][0] - m0);
            s[j][1] = ex2(s[j][1] - m0);
            s[j][2] = ex2(s[j][2] - m1);
            s[j][3] = ex2(s[j][3] - m1);
            ps0 += s[j][0] + s[j][1];
            ps1 += s[j][2] + s[j][3];
        }
        ps0 += __shfl_xor_sync(0xffffffffu, ps0, 1);
        ps0 += __shfl_xor_sync(0xffffffffu, ps0, 2);
        ps1 += __shfl_xor_sync(0xffffffffu, ps1, 1);
        ps1 += __shfl_xor_sync(0xffffffffu, ps1, 2);
        l0 = l0 * corr0 + ps0;
        l1 = l1 * corr1 + ps1;

        if (__any_sync(0xffffffffu, upd)) {
            #pragma unroll
            for (int nt = 0; nt < 16; nt++) {
                o[nt][0] *= corr0; o[nt][1] *= corr0;
                o[nt][2] *= corr1; o[nt][3] *= corr1;
            }
        }

        // ---- O += P16 V16 over 64 keys ----
        #pragma unroll
        for (int ks2 = 0; ks2 < 4; ks2++) {
            uint32_t ph[4];
            ph[0] = pack_h2(s[2*ks2][0],   s[2*ks2][1]);
            ph[1] = pack_h2(s[2*ks2][2],   s[2*ks2][3]);
            ph[2] = pack_h2(s[2*ks2+1][0], s[2*ks2+1][1]);
            ph[3] = pack_h2(s[2*ks2+1][2], s[2*ks2+1][3]);
            #pragma unroll
            for (int dp = 0; dp < 8; dp++) {
                uint32_t vh[4];
                uint32_t addr = sb + 1*KTB64 + (uint32_t)(16 * ks2) * AVP + dp * 32 + v_add;
                ldsm_x4_t(vh[0], vh[1], vh[2], vh[3], addr);
                mma_f16(o[2*dp],   ph, vh[0], vh[1]);
                mma_f16(o[2*dp+1], ph, vh[2], vh[3]);
            }
        }
        __syncthreads();
    }

    // ---- epilogue: normalize, single fp16 out ----
    const float inv0 = 1.f / l0, inv1 = 1.f / l1;
    const size_t ob0 = (size_t)(b * SQ + row0) * HD + hc;
    const size_t ob1 = ob0 + (size_t)8 * HD;
    #pragma unroll
    for (int nt = 0; nt < 16; nt++) {
        int col = 8 * nt + c2;
        *(uint32_t*)&A16[ob0 + col] = pack_h2(o[nt][0] * inv0, o[nt][1] * inv0);
        *(uint32_t*)&A16[ob1 + col] = pack_h2(o[nt][2] * inv1, o[nt][3] * inv1);
    }
}

// ---------------------------------------------------------------------------

extern "C" void kernel_launch(void* const* d_in, const int* in_sizes, int n_in,
                              void* d_out, int out_size)
{
    const float* X   = (const float*)d_in[0];
    const int*   msk = (const int*)  d_in[1];
    const float* Wq  = (const float*)d_in[2];
    const float* bq  = (const float*)d_in[3];
    const float* Wk  = (const float*)d_in[4];
    const float* bk  = (const float*)d_in[5];
    const float* Wv  = (const float*)d_in[6];
    const float* bv  = (const float*)d_in[7];
    const float* Wo  = (const float*)d_in[8];
    const float* bo  = (const float*)d_in[9];
    float* out = (float*)d_out;

    __half *Q16, *K16, *V16, *A16, *X16, *Wt;
    uint32_t* Mb;
    cudaGetSymbolAddress((void**)&Q16, g_Q16);
    cudaGetSymbolAddress((void**)&K16, g_K16);
    cudaGetSymbolAddress((void**)&V16, g_V16);
    cudaGetSymbolAddress((void**)&A16, g_A16);
    cudaGetSymbolAddress((void**)&X16, g_X16);
    cudaGetSymbolAddress((void**)&Wt,  g_Wt);
    cudaGetSymbolAddress((void**)&Mb,  g_Mbits);

    const size_t WSZ = (size_t)HD * HD;
    const int n4 = MR * HD / 4;
    const int nwords = MR * SQ / 32;   // 262144

    cudaFuncSetAttribute(gemm_mma_kernel<0>,
                         cudaFuncAttributeMaxDynamicSharedMemorySize, GEMM_SMEM);
    cudaFuncSetAttribute(gemm_mma_kernel<1>,
                         cudaFuncAttributeMaxDynamicSharedMemorySize, GEMM_SMEM);
    cudaFuncSetAttribute(attn_mma_kernel,
                         cudaFuncAttributeMaxDynamicSharedMemorySize, ATTN_SMEM);

    // 1. X -> fp16; weights -> fp16 (transposed); mask -> bitmask
    cvt_h_kernel<<<n4 / 256, 256>>>((const float4*)X, X16, n4);
    dim3 wg(HD / 32, HD / 32, 4), wb(32, 8);
    cvt_wt_kernel<<<wg, wb>>>(Wq, Wk, Wv, Wo, Wt);
    cvt_mask_kernel<<<nwords / 256, 256>>>(msk, Mb, nwords);

    // 2. Fused Q/K/V projection (1-MMA, 64x64 warp tiles) -> fp16 outputs
    dim3 gq(3 * HD / 128, MR / 128);   // (48, 32)
    gemm_mma_kernel<0><<<gq, 128, GEMM_SMEM>>>(
        X16, Wt, bq, bk, bv, Q16, K16, V16, nullptr);

    // 3. fp16 1-MMA flash attention (64-key chunks, bitmask) -> fp16 A
    dim3 ga(SQ / 64, NH, BB);          // (32, 16, 2)
    attn_mma_kernel<<<ga, 128, ATTN_SMEM>>>(Q16, K16, V16, Mb, A16);

    // 4. output projection (1-MMA) -> fp32 out
    dim3 go(HD / 128, MR / 128);       // (16, 32)
    gemm_mma_kernel<1><<<go, 128, GEMM_SMEM>>>(
        A16, Wt + 3*WSZ, bo, bo, bo,
        nullptr, nullptr, nullptr, out);
}